// round 2
// baseline (speedup 1.0000x reference)
#include <cuda_runtime.h>
#include <math.h>

#define NQ     12
#define DIM    4096
#define NT     32
#define NB     64
#define NBT    2048            // NB * NT
#define NROTS  96
#define DEG    4

// -------- device scratch (static allocation only; no cudaMalloc allowed) ----
__device__ float2 g_cs[NBT * NROTS];     // cos/sin(theta/2) per (b,t,rot)   1.5 MB
__device__ float2 g_work[NB * DIM];      // current polynomial "work" state  2 MB
__device__ float2 g_acc[NB * DIM];       // accumulator                       2 MB
__device__ float2 g_ev[(size_t)NBT * DIM]; // per-(b,t) evolved states       64 MB

// padded shared-memory accessor: +1 float2 every 16 to avoid bank conflicts
// in the stride-16 register-fused RY passes.
#define PSI(i)   psi[(i) + ((i) >> 4)]
#define PSI_PAD  (DIM + DIM / 16)

// ---------------------------------------------------------------------------
// Fused RY pass: applies the 4 RY rotations on qubit-bits [g, g+4) in
// registers. Each of the 256 threads owns the 16 amplitudes spanning those
// 4 bits. Qubit q maps to bit (11-q); ring angle index for bit (g+k) is
// idx_base + (11-g-k).  Requires blockDim.x == 256.
// ---------------------------------------------------------------------------
__device__ __forceinline__ void ry_group(float2* psi, const float2* cs,
                                         int idx_base, int g) {
    const int tid  = threadIdx.x;
    const int base = ((tid >> g) << (g + 4)) | (tid & ((1 << g) - 1));
    float2 v[16];
#pragma unroll
    for (int l = 0; l < 16; ++l) { int i = base + (l << g); v[l] = PSI(i); }
#pragma unroll
    for (int k = 0; k < 4; ++k) {
        float2 a = cs[idx_base + (11 - g - k)];
        const float c = a.x, s = a.y;
#pragma unroll
        for (int l = 0; l < 16; ++l) {
            if (l & (1 << k)) continue;
            const int l1 = l | (1 << k);
            float2 a0 = v[l], a1 = v[l1];
            v[l]  = make_float2(c * a0.x - s * a1.x, c * a0.y - s * a1.y);
            v[l1] = make_float2(s * a0.x + c * a1.x, s * a0.y + c * a1.y);
        }
    }
#pragma unroll
    for (int l = 0; l < 16; ++l) { int i = base + (l << g); PSI(i) = v[l]; }
}

// CRX(control, target): acts on the half of the state with control bit = 1.
//   a0' = c*a0 - i*s*a1 ;  a1' = c*a1 - i*s*a0
__device__ __forceinline__ void crx_gate(float2* psi, float c, float s,
                                         int ctrl, int tgt) {
    const int b1 = 11 - ctrl, b2 = 11 - tgt;
    const int lo = (b1 < b2) ? b1 : b2;
    const int hi = b1 ^ b2 ^ lo;
    const int mc = 1 << b1, mt = 1 << b2;
#pragma unroll
    for (int p = threadIdx.x; p < 1024; p += 256) {
        int i = ((p >> lo) << (lo + 1)) | (p & ((1 << lo) - 1));
        i = ((i >> hi) << (hi + 1)) | (i & ((1 << hi) - 1));
        i |= mc;
        float2 a0 = PSI(i), a1 = PSI(i + mt);
        PSI(i)      = make_float2(c * a0.x + s * a1.y, c * a0.y - s * a1.x);
        PSI(i + mt) = make_float2(c * a1.x + s * a0.y, c * a1.y - s * a0.x);
    }
}

// sim14 ansatz (Sim et al. 2019), `layers` layers, 48 angles per layer.
__device__ __forceinline__ void apply_circuit(float2* psi, const float2* cs,
                                              int layers) {
    int idx = 0;
    for (int L = 0; L < layers; ++L) {
        // RY ring (qubits 0..11) — fused, 3 passes
        __syncthreads(); ry_group(psi, cs, idx, 0);
        __syncthreads(); ry_group(psi, cs, idx, 4);
        __syncthreads(); ry_group(psi, cs, idx, 8);
        idx += 12;
        // reversed CRX ring: control i = 11..0, target (i+1)%12
        for (int i = 11; i >= 0; --i) {
            __syncthreads();
            crx_gate(psi, cs[idx].x, cs[idx].y, i, (i + 1) % 12);
            ++idx;
        }
        // RY ring again
        __syncthreads(); ry_group(psi, cs, idx, 0);
        __syncthreads(); ry_group(psi, cs, idx, 4);
        __syncthreads(); ry_group(psi, cs, idx, 8);
        idx += 12;
        // rotated CRX ring: i = 11, 0, 1, ..., 10 ; target (i-1)%12
        {
            __syncthreads();
            crx_gate(psi, cs[idx].x, cs[idx].y, 11, 10);
            ++idx;
        }
        for (int i = 0; i < 11; ++i) {
            __syncthreads();
            crx_gate(psi, cs[idx].x, cs[idx].y, i, (i + 11) % 12);
            ++idx;
        }
    }
    __syncthreads();
}

// ---------------------------------------------------------------------------
// Kernel 1: angles -> cos/sin(theta/2).  theta = sigmoid(x@W^T + b) * 2pi.
// grid = 2048 (b*t), block = 96 (one rot each).
// ---------------------------------------------------------------------------
__global__ void prep_kernel(const float* __restrict__ x,
                            const float* __restrict__ W,
                            const float* __restrict__ bias) {
    const int bt = blockIdx.x;
    const int r  = threadIdx.x;
    const float* xr = x + bt * 64;
    const float* wr = W + r * 64;
    float acc = bias[r];
#pragma unroll
    for (int k = 0; k < 64; ++k) acc += xr[k] * wr[k];
    const float sig = 1.0f / (1.0f + expf(-acc));
    const float h   = sig * 3.14159265358979323846f;   // theta/2
    float s, c;
    sincosf(h, &s, &c);
    g_cs[bt * NROTS + r] = make_float2(c, s);
}

// Kernel 2: work = |0..0>, acc = poly[0] * |0..0>.
__global__ void init_kernel(const float* __restrict__ poly) {
    const int i = blockIdx.x * 256 + threadIdx.x;     // 64*4096 threads
    const float p0 = poly[0];
    const bool head = (i & (DIM - 1)) == 0;
    g_work[i] = head ? make_float2(1.0f, 0.0f) : make_float2(0.0f, 0.0f);
    g_acc[i]  = head ? make_float2(p0, 0.0f)   : make_float2(0.0f, 0.0f);
}

// Kernel 3: one (b,t) circuit per CTA; state lives in padded smem.
__global__ __launch_bounds__(256) void sim_kernel() {
    __shared__ float2 psi[PSI_PAD];
    __shared__ float2 cs[NROTS];
    const int bt = blockIdx.x;
    const int b  = bt >> 5;
    const float2* src = g_work + (size_t)b * DIM;
    for (int i = threadIdx.x; i < DIM; i += 256) PSI(i) = src[i];
    for (int i = threadIdx.x; i < NROTS; i += 256) cs[i] = g_cs[bt * NROTS + i];
    apply_circuit(psi, cs, 2);           // starts & ends with __syncthreads
    float2* dst = g_ev + (size_t)bt * DIM;
    for (int i = threadIdx.x; i < DIM; i += 256) dst[i] = PSI(i);
}

// Kernel 4: work[b] = sum_t mix[t]*ev[b,t] ;  acc += poly[k]*work.
__global__ void reduce_kernel(const float* __restrict__ mix_re,
                              const float* __restrict__ mix_im,
                              const float* __restrict__ poly, int k) {
    __shared__ float2 smix[NT];
    if (threadIdx.x < NT)
        smix[threadIdx.x] = make_float2(mix_re[threadIdx.x], mix_im[threadIdx.x]);
    __syncthreads();
    const int i = blockIdx.x * 256 + threadIdx.x;     // over 64*4096
    const int b = i >> 12;
    const int a = i & (DIM - 1);
    const float2* e = g_ev + (size_t)(b * NT) * DIM + a;
    float wr = 0.0f, wi = 0.0f;
#pragma unroll
    for (int t = 0; t < NT; ++t) {
        float2 v = e[(size_t)t * DIM];
        float2 m = smix[t];
        wr += m.x * v.x - m.y * v.y;
        wi += m.x * v.y + m.y * v.x;
    }
    g_work[i] = make_float2(wr, wi);
    const float pk = poly[k];
    float2 ac = g_acc[i];
    g_acc[i] = make_float2(ac.x + pk * wr, ac.y + pk * wi);
}

// Kernel 5: normalize acc, QFF circuit (1 layer), Pauli expvals, output head.
__global__ __launch_bounds__(256) void final_kernel(
        const float* __restrict__ poly, const float* __restrict__ qff,
        const float* __restrict__ W_out, const float* __restrict__ b_out,
        float* __restrict__ out) {
    __shared__ float2 psi[PSI_PAD];
    __shared__ float2 cs[48];
    __shared__ float wred[8][3];
    __shared__ float exps[36];
    __shared__ float s_scale;
    const int b = blockIdx.x, tid = threadIdx.x;
    const int lane = tid & 31, wid = tid >> 5;

    // load acc into smem, accumulate |acc|^2
    const float2* src = g_acc + (size_t)b * DIM;
    float ss = 0.0f;
    for (int i = tid; i < DIM; i += 256) {
        float2 v = src[i];
        PSI(i) = v;
        ss += v.x * v.x + v.y * v.y;
    }
#pragma unroll
    for (int o = 16; o > 0; o >>= 1) ss += __shfl_down_sync(0xffffffffu, ss, o);
    if (lane == 0) wred[wid][0] = ss;
    __syncthreads();
    if (tid == 0) {
        float tot = 0.0f;
        for (int w = 0; w < 8; ++w) tot += wred[w][0];
        float sp = 0.0f;
        for (int j = 0; j <= DEG; ++j) sp += fabsf(poly[j]);
        // acc/s then /(norm+1e-9)  ==  acc/(||acc|| + 1e-9*s)
        s_scale = 1.0f / (sqrtf(tot) + 1e-9f * sp);
    }
    if (tid < 48) {
        float s, c;
        sincosf(qff[tid] * 0.5f, &s, &c);
        cs[tid] = make_float2(c, s);
    }
    __syncthreads();
    const float scl = s_scale;
    for (int i = tid; i < DIM; i += 256) {
        float2 v = PSI(i);
        PSI(i) = make_float2(v.x * scl, v.y * scl);
    }

    apply_circuit(psi, cs, 1);           // QFF layer

    // Pauli expectation values: X_w, Y_w, Z_w
    for (int w = 0; w < NQ; ++w) {
        const int bw = 11 - w, m = 1 << bw;
        float zr = 0.0f, zi = 0.0f, zz = 0.0f;
#pragma unroll
        for (int p = tid; p < 2048; p += 256) {
            int i = ((p >> bw) << (bw + 1)) | (p & (m - 1));
            float2 a0 = PSI(i), a1 = PSI(i + m);
            zr += a0.x * a1.x + a0.y * a1.y;
            zi += a0.x * a1.y - a0.y * a1.x;
            zz += a0.x * a0.x + a0.y * a0.y - a1.x * a1.x - a1.y * a1.y;
        }
#pragma unroll
        for (int o = 16; o > 0; o >>= 1) {
            zr += __shfl_down_sync(0xffffffffu, zr, o);
            zi += __shfl_down_sync(0xffffffffu, zi, o);
            zz += __shfl_down_sync(0xffffffffu, zz, o);
        }
        if (lane == 0) { wred[wid][0] = zr; wred[wid][1] = zi; wred[wid][2] = zz; }
        __syncthreads();
        if (tid == 0) {
            float sr = 0.0f, si = 0.0f, sz = 0.0f;
            for (int q = 0; q < 8; ++q) {
                sr += wred[q][0]; si += wred[q][1]; sz += wred[q][2];
            }
            exps[w]      = 2.0f * sr;
            exps[12 + w] = 2.0f * si;
            exps[24 + w] = sz;
        }
        __syncthreads();
    }

    if (tid < 8) {
        float o = b_out[tid];
#pragma unroll
        for (int j = 0; j < 36; ++j) o += exps[j] * W_out[tid * 36 + j];
        out[b * 8 + tid] = o;
    }
}

// ---------------------------------------------------------------------------
extern "C" void kernel_launch(void* const* d_in, const int* in_sizes, int n_in,
                              void* d_out, int out_size) {
    const float* x      = (const float*)d_in[0];
    const float* W_proj = (const float*)d_in[1];
    const float* b_proj = (const float*)d_in[2];
    const float* poly   = (const float*)d_in[3];
    const float* mix_re = (const float*)d_in[4];
    const float* mix_im = (const float*)d_in[5];
    const float* qff    = (const float*)d_in[6];
    const float* W_out  = (const float*)d_in[7];
    const float* b_out  = (const float*)d_in[8];
    float* out = (float*)d_out;

    prep_kernel<<<NBT, NROTS>>>(x, W_proj, b_proj);
    init_kernel<<<NB * DIM / 256, 256>>>(poly);
    for (int k = 1; k <= DEG; ++k) {
        sim_kernel<<<NBT, 256>>>();
        reduce_kernel<<<NB * DIM / 256, 256>>>(mix_re, mix_im, poly, k);
    }
    final_kernel<<<NB, 256>>>(poly, qff, W_out, b_out, out);
}